// round 16
// baseline (speedup 1.0000x reference)
#include <cuda_runtime.h>
#include <cuda_bf16.h>
#include <cuda_fp16.h>
#include <math.h>
#include <stdint.h>

#define D_MODEL 1024
#define NHEADS  16
#define DH      64
#define SEQ     2048
#define BATCH   2
#define WIN     128
#define MROWS   (BATCH * SEQ)   // 4096

// ---------------- scratch (static device memory) ----------------
__device__ __half g_q [MROWS * D_MODEL];
__device__ __half g_k [MROWS * D_MODEL];
__device__ __half g_v [MROWS * D_MODEL];

__device__ __half g_xf [MROWS * D_MODEL];
__device__ __half g_wf [3 * D_MODEL * D_MODEL];
__device__ __half g_wof[D_MODEL * D_MODEL];
__device__ __half g_aof[MROWS * D_MODEL];

// ---------------- PTX helpers ----------------
__device__ __forceinline__ uint32_t smem_u32(const void* p) {
    uint32_t a;
    asm("{ .reg .u64 t; cvta.to.shared.u64 t, %1; cvt.u32.u64 %0, t; }"
        : "=r"(a) : "l"(p));
    return a;
}
#define CPA16(dst, src) \
    asm volatile("cp.async.cg.shared.global [%0], [%1], 16;" :: "r"(dst), "l"(src))
#define CPA_COMMIT() asm volatile("cp.async.commit_group;" ::: "memory")
#define CPA_WAIT1()  asm volatile("cp.async.wait_group 1;" ::: "memory")
#define CPA_WAIT0()  asm volatile("cp.async.wait_group 0;" ::: "memory")

#define LDM4(r, addr) \
    asm volatile("ldmatrix.sync.aligned.m8n8.x4.shared.b16 {%0,%1,%2,%3}, [%4];" \
        : "=r"((r)[0]), "=r"((r)[1]), "=r"((r)[2]), "=r"((r)[3]) : "r"(addr))

#define LDM4T(r, addr) \
    asm volatile("ldmatrix.sync.aligned.m8n8.x4.trans.shared.b16 {%0,%1,%2,%3}, [%4];" \
        : "=r"((r)[0]), "=r"((r)[1]), "=r"((r)[2]), "=r"((r)[3]) : "r"(addr))

#define MMAF16(acc, a, b0, b1) \
    asm volatile("mma.sync.aligned.m16n8k16.row.col.f32.f16.f16.f32 " \
        "{%0,%1,%2,%3}, {%4,%5,%6,%7}, {%8,%9}, {%0,%1,%2,%3};" \
        : "+f"((acc)[0]), "+f"((acc)[1]), "+f"((acc)[2]), "+f"((acc)[3]) \
        : "r"((a)[0]), "r"((a)[1]), "r"((a)[2]), "r"((a)[3]), "r"(b0), "r"(b1))

// ---------------------------------------------------------------------------
// Conversions: fp32 -> fp16, 16 floats / thread (MLP=4).
// blocks [0,1024): x ; [1024,2048): Wq/Wk/Wv/Wo (256 blocks each).
// ---------------------------------------------------------------------------
__global__ __launch_bounds__(256)
void conv_all(const float* __restrict__ x,
              const float* __restrict__ Wq, const float* __restrict__ Wk,
              const float* __restrict__ Wv, const float* __restrict__ Wo)
{
    int blk = blockIdx.x;
    const float* src;
    __half* dst;
    int i;   // index in 16-float units
    if (blk < 1024) {
        src = x; dst = g_xf; i = blk * 256 + threadIdx.x;
    } else {
        int w  = (blk - 1024) >> 8;
        int bb = (blk - 1024) & 255;
        src = (w == 0) ? Wq : (w == 1) ? Wk : (w == 2) ? Wv : Wo;
        dst = (w == 3) ? g_wof : (g_wf + (size_t)w * D_MODEL * D_MODEL);
        i = bb * 256 + threadIdx.x;
    }

    float4 f0 = ((const float4*)src)[i * 4];
    float4 f1 = ((const float4*)src)[i * 4 + 1];
    float4 f2 = ((const float4*)src)[i * 4 + 2];
    float4 f3 = ((const float4*)src)[i * 4 + 3];
    __half2 h0 = __floats2half2_rn(f0.x, f0.y), h1 = __floats2half2_rn(f0.z, f0.w);
    __half2 h2 = __floats2half2_rn(f1.x, f1.y), h3 = __floats2half2_rn(f1.z, f1.w);
    __half2 h4 = __floats2half2_rn(f2.x, f2.y), h5 = __floats2half2_rn(f2.z, f2.w);
    __half2 h6 = __floats2half2_rn(f3.x, f3.y), h7 = __floats2half2_rn(f3.z, f3.w);
    uint4 o0 = { *(uint32_t*)&h0, *(uint32_t*)&h1, *(uint32_t*)&h2, *(uint32_t*)&h3 };
    uint4 o1 = { *(uint32_t*)&h4, *(uint32_t*)&h5, *(uint32_t*)&h6, *(uint32_t*)&h7 };
    ((uint4*)dst)[i * 2]     = o0;
    ((uint4*)dst)[i * 2 + 1] = o1;
}

// ---------------------------------------------------------------------------
// Single-pass fp16 GEMM (R14 pipeline): 128x128 tile, 8 warps, K-chunks of 64,
// 3-stage cp.async, pipelined fragments, 2 CTAs/SM.
// mode 0: C = g_q/g_k/g_v (fp16).  mode 1: C = out_direct (fp32).
// ---------------------------------------------------------------------------
#define F16_TILE  16384
#define F16_STAGE 32768
#define F16_NST   3
#define SMEM_F16  (F16_NST * F16_STAGE + 1024)

__global__ __launch_bounds__(256, 2)
void gemm_f16(const float* __restrict__ b0, const float* __restrict__ b1,
              const float* __restrict__ b2, float* __restrict__ out_direct, int mode)
{
    extern __shared__ char dsm_raw[];
    char* sm = (char*)(((uintptr_t)dsm_raw + 1023) & ~(uintptr_t)1023);
    const uint32_t sb = smem_u32(sm);
    const int tid = threadIdx.x, wid = tid >> 5, lane = tid & 31;
    const int bn = blockIdx.x * 128, bm = blockIdx.y * 128, z = blockIdx.z;

    const __half *A, *W;
    if (mode == 0) {
        A = g_xf;
        W = g_wf + (size_t)z * D_MODEL * D_MODEL;
    } else {
        A = g_aof;
        W = g_wof;
    }

    const int r = tid >> 1;
    const int half_ = tid & 1;
    const __half* srcA = A + (size_t)(bm + r) * D_MODEL + half_ * 32;
    const __half* srcW = W + (size_t)(bn + r) * D_MODEL + half_ * 32;
    uint32_t sts_off[4];
#pragma unroll
    for (int s = 0; s < 4; s++) {
        uint32_t u = (uint32_t)(half_ * 4 + s);
        sts_off[s] = (uint32_t)r * 128 + ((u ^ ((uint32_t)r & 7)) << 4);
    }

    const int wm = (wid & 1) * 64;
    const int wn = (wid >> 1) * 32;

    float acc[4][4][4];
#pragma unroll
    for (int mi = 0; mi < 4; mi++)
#pragma unroll
        for (int nj = 0; nj < 4; nj++)
#pragma unroll
            for (int q = 0; q < 4; q++) acc[mi][nj][q] = 0.f;

    const uint32_t lrow = lane & 15;
    const uint32_t lsel = lane >> 4;

#pragma unroll
    for (int pc = 0; pc < 2; pc++) {
        uint32_t stb = sb + (uint32_t)pc * F16_STAGE;
#pragma unroll
        for (int s = 0; s < 4; s++) {
            CPA16(stb + sts_off[s],            srcA + pc * 64 + s * 8);
            CPA16(stb + F16_TILE + sts_off[s], srcW + pc * 64 + s * 8);
        }
        CPA_COMMIT();
    }

    int stage_c = 0;
    int stage_n = 2;
    for (int c = 0; c < 16; c++) {
        if (c == 15) { CPA_WAIT0(); } else { CPA_WAIT1(); }
        __syncthreads();

        if (c + 2 < 16) {
            uint32_t stb = sb + (uint32_t)stage_n * F16_STAGE;
#pragma unroll
            for (int s = 0; s < 4; s++) {
                CPA16(stb + sts_off[s],            srcA + (c + 2) * 64 + s * 8);
                CPA16(stb + F16_TILE + sts_off[s], srcW + (c + 2) * 64 + s * 8);
            }
            CPA_COMMIT();
        }

        const uint32_t stg = sb + (uint32_t)stage_c * F16_STAGE;
#pragma unroll
        for (int kk = 0; kk < 4; kk++) {
            const uint32_t kb = (uint32_t)kk * 2 + lsel;
            uint32_t rw0 = (uint32_t)wn + lrow;
            uint32_t rw1 = (uint32_t)(wn + 16) + lrow;
            uint32_t ra0 = (uint32_t)wm + lrow;
            uint32_t ra1 = (uint32_t)(wm + 16) + lrow;
            uint32_t ra2 = (uint32_t)(wm + 32) + lrow;
            uint32_t ra3 = (uint32_t)(wm + 48) + lrow;

            uint32_t bh0[4], bh1[4], a0[4], a1[4], a2[4], a3[4];
            LDM4(bh0, stg + F16_TILE + rw0 * 128 + ((kb ^ (rw0 & 7)) << 4));
            LDM4(bh1, stg + F16_TILE + rw1 * 128 + ((kb ^ (rw1 & 7)) << 4));
            LDM4(a0, stg + ra0 * 128 + ((kb ^ (ra0 & 7)) << 4));
            LDM4(a1, stg + ra1 * 128 + ((kb ^ (ra1 & 7)) << 4));

            MMAF16(acc[0][0], a0, bh0[0], bh0[2]);
            MMAF16(acc[0][1], a0, bh0[1], bh0[3]);
            LDM4(a2, stg + ra2 * 128 + ((kb ^ (ra2 & 7)) << 4));
            MMAF16(acc[0][2], a0, bh1[0], bh1[2]);
            MMAF16(acc[0][3], a0, bh1[1], bh1[3]);

            MMAF16(acc[1][0], a1, bh0[0], bh0[2]);
            MMAF16(acc[1][1], a1, bh0[1], bh0[3]);
            LDM4(a3, stg + ra3 * 128 + ((kb ^ (ra3 & 7)) << 4));
            MMAF16(acc[1][2], a1, bh1[0], bh1[2]);
            MMAF16(acc[1][3], a1, bh1[1], bh1[3]);

            MMAF16(acc[2][0], a2, bh0[0], bh0[2]);
            MMAF16(acc[2][1], a2, bh0[1], bh0[3]);
            MMAF16(acc[2][2], a2, bh1[0], bh1[2]);
            MMAF16(acc[2][3], a2, bh1[1], bh1[3]);
            MMAF16(acc[3][0], a3, bh0[0], bh0[2]);
            MMAF16(acc[3][1], a3, bh0[1], bh0[3]);
            MMAF16(acc[3][2], a3, bh1[0], bh1[2]);
            MMAF16(acc[3][3], a3, bh1[1], bh1[3]);
        }
        stage_c = (stage_c == F16_NST - 1) ? 0 : stage_c + 1;
        stage_n = (stage_n == F16_NST - 1) ? 0 : stage_n + 1;
    }

    if (mode == 0) {
        const float* bias = (z == 0) ? b0 : ((z == 1) ? b1 : b2);
        __half* C = (z == 0) ? g_q : ((z == 1) ? g_k : g_v);
#pragma unroll
        for (int mi = 0; mi < 4; mi++) {
            const int orow = bm + wm + mi * 16 + (lane >> 2);
#pragma unroll
            for (int nj = 0; nj < 4; nj++) {
                const int col = bn + wn + nj * 8 + ((lane & 3) << 1);
                __half2 o0 = __floats2half2_rn(acc[mi][nj][0] + bias[col],
                                               acc[mi][nj][1] + bias[col + 1]);
                __half2 o1 = __floats2half2_rn(acc[mi][nj][2] + bias[col],
                                               acc[mi][nj][3] + bias[col + 1]);
                *(uint32_t*)&C[(size_t)orow * D_MODEL + col]       = *(uint32_t*)&o0;
                *(uint32_t*)&C[(size_t)(orow + 8) * D_MODEL + col] = *(uint32_t*)&o1;
            }
        }
    } else {
        const float* bias = b0;
        float* C = out_direct;
#pragma unroll
        for (int mi = 0; mi < 4; mi++) {
            const int orow = bm + wm + mi * 16 + (lane >> 2);
#pragma unroll
            for (int nj = 0; nj < 4; nj++) {
                const int col = bn + wn + nj * 8 + ((lane & 3) << 1);
                float2 o0 = { acc[mi][nj][0] + bias[col], acc[mi][nj][1] + bias[col + 1] };
                float2 o1 = { acc[mi][nj][2] + bias[col], acc[mi][nj][3] + bias[col + 1] };
                *(float2*)&C[(size_t)orow * D_MODEL + col]       = o0;
                *(float2*)&C[(size_t)(orow + 8) * D_MODEL + col] = o1;
            }
        }
    }
}

// ---------------------------------------------------------------------------
// fp16 flash attention, fused RoPE.  256 threads (8 warps), 128 queries/CTA,
// K/V chunks of 64.  Warps 0-3 produce K (rope), warps 4-7 produce V.
// ---------------------------------------------------------------------------
__device__ __forceinline__ void rope16(float* x1, float* x2, int s, int cb, float scale) {
#pragma unroll
    for (int i = 0; i < 16; i++) {
        float invf = exp2f(-(float)(cb + i) * (13.2877123795494f / 32.f));
        float ang = (float)s * invf;
        float sn, cs;
        sincosf(ang, &sn, &cs);
        float o1 = (x1[i] * cs - x2[i] * sn) * scale;
        float o2 = (x1[i] * sn + x2[i] * cs) * scale;
        x1[i] = o1; x2[i] = o2;
    }
}

__device__ __forceinline__ void ld16h(const __half* p, float* f) {
    uint4 u0 = *(const uint4*)p;
    uint4 u1 = *(const uint4*)(p + 8);
    const uint32_t w[8] = { u0.x, u0.y, u0.z, u0.w, u1.x, u1.y, u1.z, u1.w };
#pragma unroll
    for (int i = 0; i < 8; i++) {
        float2 t = __half22float2(*(const __half2*)&w[i]);
        f[2 * i] = t.x; f[2 * i + 1] = t.y;
    }
}

__device__ __forceinline__ void store_h(char* base, int row, int cb, const float* v) {
#pragma unroll
    for (int i = 0; i < 16; i += 2) {
        uint32_t off = (uint32_t)row * 128 + (uint32_t)(cb + i) * 2;
        off ^= ((uint32_t)row & 7) << 4;
        __half2 p = __floats2half2_rn(v[i], v[i + 1]);
        *(uint32_t*)(base + off) = *(uint32_t*)&p;
    }
}

#define ATT_Q 128

__global__ __launch_bounds__(256)
void attn_tc()
{
    __shared__ __align__(16) char sdata[32768];
    char* sQ = sdata;            // 128 x 64 fp16 = 16KB
    char* sK = sdata + 16384;    // 64 x 64 fp16 = 8KB
    char* sV = sdata + 24576;    // 8KB
    const uint32_t sb = smem_u32(sdata);

    const int tid = threadIdx.x, wid = tid >> 5, lane = tid & 31;
    const int q0 = blockIdx.x * ATT_Q, h = blockIdx.y, b = blockIdx.z;
    const __half* Qg = g_q + (size_t)b * SEQ * D_MODEL + h * DH;
    const __half* Kg = g_k + (size_t)b * SEQ * D_MODEL + h * DH;
    const __half* Vg = g_v + (size_t)b * SEQ * D_MODEL + h * DH;

    // ---- Q: 256 threads load 128 rows, rope + scale, store fp16 ----
    {
        const int lrw = tid >> 1;
        const int lch = (tid & 1) * 16;
        const __half* qp = Qg + (size_t)(q0 + lrw) * D_MODEL;
        float x1[16], x2[16];
        ld16h(qp + lch, x1);
        ld16h(qp + lch + 32, x2);
        rope16(x1, x2, q0 + lrw, lch, 0.125f);
        store_h(sQ, lrw, lch, x1);
        store_h(sQ, lrw, lch + 32, x2);
    }

    const int wq = wid * 16;
    float m0 = -1e30f, m1 = -1e30f, l0 = 0.f, l1 = 0.f;
    float acc[8][4];
#pragma unroll
    for (int nb = 0; nb < 8; nb++)
#pragma unroll
        for (int q = 0; q < 4; q++) acc[nb][q] = 0.f;

    int kv0 = q0 - WIN; if (kv0 < 0) kv0 = 0;
    const int nk = q0 + ATT_Q - kv0;   // 128 or 256

    const int qg0 = q0 + wq + (lane >> 2);
    const int qg1 = qg0 + 8;

    for (int kb = 0; kb < nk; kb += 64) {
        const int kbase = kv0 + kb;

        __syncthreads();
        // ---- warps 0-3: K rope; warps 4-7: V copy (64 rows each) ----
        if (wid < 4) {
            const int lrw = tid >> 1;              // 0..63
            const int lch = (tid & 1) * 16;
            const __half* kp = Kg + (size_t)(kbase + lrw) * D_MODEL;
            float x1[16], x2[16];
            ld16h(kp + lch, x1);
            ld16h(kp + lch + 32, x2);
            rope16(x1, x2, kbase + lrw, lch, 1.0f);
            store_h(sK, lrw, lch, x1);
            store_h(sK, lrw, lch + 32, x2);
        } else {
            const int t = tid - 128;
            const int lrw = t >> 1;                // 0..63
            const int vc = (t & 1) * 32;
            const __half* vp = Vg + (size_t)(kbase + lrw) * D_MODEL;
            float va[16], vb[16];
            ld16h(vp + vc, va);
            ld16h(vp + vc + 16, vb);
            store_h(sV, lrw, vc, va);
            store_h(sV, lrw, vc + 16, vb);
        }
        __syncthreads();

        // ---- S = Q K^T ----
        float S[8][4];
#pragma unroll
        for (int nb = 0; nb < 8; nb++)
#pragma unroll
            for (int q = 0; q < 4; q++) S[nb][q] = 0.f;

#pragma unroll
        for (int ks = 0; ks < 4; ks++) {
            const uint32_t acb  = (uint32_t)ks * 32 + ((uint32_t)(lane >> 4) << 4);
            const uint32_t arow = (uint32_t)wq + (lane & 15);
            const uint32_t aoff = arow * 128 + (acb ^ ((arow & 7) << 4));
            uint32_t ah[4];
            LDM4(ah, sb + aoff);
#pragma unroll
            for (int nb2 = 0; nb2 < 4; nb2++) {
                const uint32_t brow = (uint32_t)nb2 * 16 + (lane & 15);
                const uint32_t boff = brow * 128 + (acb ^ ((brow & 7) << 4));
                uint32_t bh[4];
                LDM4(bh, sb + 16384 + boff);
                MMAF16(S[nb2 * 2],     ah, bh[0], bh[2]);
                MMAF16(S[nb2 * 2 + 1], ah, bh[1], bh[3]);
            }
        }

        // ---- mask + online softmax ----
#pragma unroll
        for (int nb = 0; nb < 8; nb++) {
            const int kg = kbase + nb * 8 + ((lane & 3) << 1);
            if (kg     > qg0 || kg     < qg0 - WIN) S[nb][0] = -1e30f;
            if (kg + 1 > qg0 || kg + 1 < qg0 - WIN) S[nb][1] = -1e30f;
            if (kg     > qg1 || kg     < qg1 - WIN) S[nb][2] = -1e30f;
            if (kg + 1 > qg1 || kg + 1 < qg1 - WIN) S[nb][3] = -1e30f;
        }
        float mx0 = -1e30f, mx1 = -1e30f;
#pragma unroll
        for (int nb = 0; nb < 8; nb++) {
            mx0 = fmaxf(mx0, fmaxf(S[nb][0], S[nb][1]));
            mx1 = fmaxf(mx1, fmaxf(S[nb][2], S[nb][3]));
        }
        mx0 = fmaxf(mx0, __shfl_xor_sync(0xffffffffu, mx0, 1));
        mx0 = fmaxf(mx0, __shfl_xor_sync(0xffffffffu, mx0, 2));
        mx1 = fmaxf(mx1, __shfl_xor_sync(0xffffffffu, mx1, 1));
        mx1 = fmaxf(mx1, __shfl_xor_sync(0xffffffffu, mx1, 2));

        const float mn0 = fmaxf(m0, mx0), mn1 = fmaxf(m1, mx1);
        const float e0 = __expf(m0 - mn0), e1 = __expf(m1 - mn1);
        m0 = mn0; m1 = mn1;

        float s0 = 0.f, s1 = 0.f;
#pragma unroll
        for (int nb = 0; nb < 8; nb++) {
            S[nb][0] = __expf(S[nb][0] - m0); s0 += S[nb][0];
            S[nb][1] = __expf(S[nb][1] - m0); s0 += S[nb][1];
            S[nb][2] = __expf(S[nb][2] - m1); s1 += S[nb][2];
            S[nb][3] = __expf(S[nb][3] - m1); s1 += S[nb][3];
        }
        s0 += __shfl_xor_sync(0xffffffffu, s0, 1);
        s0 += __shfl_xor_sync(0xffffffffu, s0, 2);
        s1 += __shfl_xor_sync(0xffffffffu, s1, 1);
        s1 += __shfl_xor_sync(0xffffffffu, s1, 2);
        l0 = l0 * e0 + s0;
        l1 = l1 * e1 + s1;
#pragma unroll
        for (int nb = 0; nb < 8; nb++) {
            acc[nb][0] *= e0; acc[nb][1] *= e0;
            acc[nb][2] *= e1; acc[nb][3] *= e1;
        }

        // ---- O += P V ----
#pragma unroll
        for (int j = 0; j < 4; j++) {
            uint32_t pa[4];
            __half2 p0 = __floats2half2_rn(S[2 * j][0],     S[2 * j][1]);
            __half2 p1 = __floats2half2_rn(S[2 * j][2],     S[2 * j][3]);
            __half2 p2 = __floats2half2_rn(S[2 * j + 1][0], S[2 * j + 1][1]);
            __half2 p3 = __floats2half2_rn(S[2 * j + 1][2], S[2 * j + 1][3]);
            pa[0] = *(uint32_t*)&p0; pa[1] = *(uint32_t*)&p1;
            pa[2] = *(uint32_t*)&p2; pa[3] = *(uint32_t*)&p3;

            const uint32_t vrow = (uint32_t)j * 16 + (lane & 15);
#pragma unroll
            for (int nb2 = 0; nb2 < 4; nb2++) {
                const uint32_t vcb = (uint32_t)nb2 * 32 + ((uint32_t)(lane >> 4) << 4);
                const uint32_t boff = vrow * 128 + (vcb ^ ((vrow & 7) << 4));
                uint32_t vh[4];
                LDM4T(vh, sb + 24576 + boff);
                MMAF16(acc[nb2 * 2],     pa, vh[0], vh[1]);
                MMAF16(acc[nb2 * 2 + 1], pa, vh[2], vh[3]);
            }
        }
    }

    // ---- epilogue: normalize, write fp16 ----
    const float inv0 = 1.f / l0, inv1 = 1.f / l1;
#pragma unroll
    for (int nb = 0; nb < 8; nb++) {
        const int col = h * DH + nb * 8 + ((lane & 3) << 1);
        const size_t i0 = ((size_t)b * SEQ + qg0) * D_MODEL + col;
        const size_t i1 = ((size_t)b * SEQ + qg1) * D_MODEL + col;
        __half2 p0 = __floats2half2_rn(acc[nb][0] * inv0, acc[nb][1] * inv0);
        __half2 p1 = __floats2half2_rn(acc[nb][2] * inv1, acc[nb][3] * inv1);
        *(uint32_t*)(g_aof + i0) = *(uint32_t*)&p0;
        *(uint32_t*)(g_aof + i1) = *(uint32_t*)&p1;
    }
}

// ---------------------------------------------------------------------------
extern "C" void kernel_launch(void* const* d_in, const int* in_sizes, int n_in,
                              void* d_out, int out_size)
{
    const float* x  = (const float*)d_in[0];
    const float* Wq = (const float*)d_in[1];
    const float* bq = (const float*)d_in[2];
    const float* Wk = (const float*)d_in[3];
    const float* bk = (const float*)d_in[4];
    const float* Wv = (const float*)d_in[5];
    const float* bv = (const float*)d_in[6];
    const float* Wo = (const float*)d_in[7];
    const float* bo = (const float*)d_in[8];
    float* out = (float*)d_out;

    cudaFuncSetAttribute(gemm_f16, cudaFuncAttributeMaxDynamicSharedMemorySize, SMEM_F16);

    conv_all<<<2048, 256>>>(x, Wq, Wk, Wv, Wo);

    gemm_f16<<<dim3(8, 32, 3), 256, SMEM_F16>>>(bq, bk, bv, nullptr, 0);

    dim3 agrid(SEQ / ATT_Q, NHEADS, BATCH);   // (16, 16, 2)
    attn_tc<<<agrid, 256>>>();

    gemm_f16<<<dim3(8, 32, 1), 256, SMEM_F16>>>(bo, nullptr, nullptr, out, 1);
}

// round 17
// speedup vs baseline: 1.0823x; 1.0823x over previous
#include <cuda_runtime.h>
#include <cuda_bf16.h>
#include <cuda_fp16.h>
#include <math.h>
#include <stdint.h>

#define D_MODEL 1024
#define NHEADS  16
#define DH      64
#define SEQ     2048
#define BATCH   2
#define WIN     128
#define MROWS   (BATCH * SEQ)   // 4096

// ---------------- scratch (static device memory) ----------------
__device__ __half g_q [MROWS * D_MODEL];
__device__ __half g_k [MROWS * D_MODEL];
__device__ __half g_v [MROWS * D_MODEL];

__device__ __half g_xf [MROWS * D_MODEL];
__device__ __half g_wf [3 * D_MODEL * D_MODEL];
__device__ __half g_wof[D_MODEL * D_MODEL];
__device__ __half g_aof[MROWS * D_MODEL];

// ---------------- PTX helpers ----------------
__device__ __forceinline__ uint32_t smem_u32(const void* p) {
    uint32_t a;
    asm("{ .reg .u64 t; cvta.to.shared.u64 t, %1; cvt.u32.u64 %0, t; }"
        : "=r"(a) : "l"(p));
    return a;
}
#define CPA16(dst, src) \
    asm volatile("cp.async.cg.shared.global [%0], [%1], 16;" :: "r"(dst), "l"(src))
#define CPA_COMMIT() asm volatile("cp.async.commit_group;" ::: "memory")
#define CPA_WAIT1()  asm volatile("cp.async.wait_group 1;" ::: "memory")
#define CPA_WAIT0()  asm volatile("cp.async.wait_group 0;" ::: "memory")

#define LDM4(r, addr) \
    asm volatile("ldmatrix.sync.aligned.m8n8.x4.shared.b16 {%0,%1,%2,%3}, [%4];" \
        : "=r"((r)[0]), "=r"((r)[1]), "=r"((r)[2]), "=r"((r)[3]) : "r"(addr))

#define LDM4T(r, addr) \
    asm volatile("ldmatrix.sync.aligned.m8n8.x4.trans.shared.b16 {%0,%1,%2,%3}, [%4];" \
        : "=r"((r)[0]), "=r"((r)[1]), "=r"((r)[2]), "=r"((r)[3]) : "r"(addr))

#define MMAF16(acc, a, b0, b1) \
    asm volatile("mma.sync.aligned.m16n8k16.row.col.f32.f16.f16.f32 " \
        "{%0,%1,%2,%3}, {%4,%5,%6,%7}, {%8,%9}, {%0,%1,%2,%3};" \
        : "+f"((acc)[0]), "+f"((acc)[1]), "+f"((acc)[2]), "+f"((acc)[3]) \
        : "r"((a)[0]), "r"((a)[1]), "r"((a)[2]), "r"((a)[3]), "r"(b0), "r"(b1))

// ---------------------------------------------------------------------------
// Conversions: fp32 -> fp16, 16 floats / thread (MLP=4).
// blocks [0,1024): x ; [1024,2048): Wq/Wk/Wv/Wo (256 blocks each).
// ---------------------------------------------------------------------------
__global__ __launch_bounds__(256)
void conv_all(const float* __restrict__ x,
              const float* __restrict__ Wq, const float* __restrict__ Wk,
              const float* __restrict__ Wv, const float* __restrict__ Wo)
{
    int blk = blockIdx.x;
    const float* src;
    __half* dst;
    int i;
    if (blk < 1024) {
        src = x; dst = g_xf; i = blk * 256 + threadIdx.x;
    } else {
        int w  = (blk - 1024) >> 8;
        int bb = (blk - 1024) & 255;
        src = (w == 0) ? Wq : (w == 1) ? Wk : (w == 2) ? Wv : Wo;
        dst = (w == 3) ? g_wof : (g_wf + (size_t)w * D_MODEL * D_MODEL);
        i = bb * 256 + threadIdx.x;
    }

    float4 f0 = ((const float4*)src)[i * 4];
    float4 f1 = ((const float4*)src)[i * 4 + 1];
    float4 f2 = ((const float4*)src)[i * 4 + 2];
    float4 f3 = ((const float4*)src)[i * 4 + 3];
    __half2 h0 = __floats2half2_rn(f0.x, f0.y), h1 = __floats2half2_rn(f0.z, f0.w);
    __half2 h2 = __floats2half2_rn(f1.x, f1.y), h3 = __floats2half2_rn(f1.z, f1.w);
    __half2 h4 = __floats2half2_rn(f2.x, f2.y), h5 = __floats2half2_rn(f2.z, f2.w);
    __half2 h6 = __floats2half2_rn(f3.x, f3.y), h7 = __floats2half2_rn(f3.z, f3.w);
    uint4 o0 = { *(uint32_t*)&h0, *(uint32_t*)&h1, *(uint32_t*)&h2, *(uint32_t*)&h3 };
    uint4 o1 = { *(uint32_t*)&h4, *(uint32_t*)&h5, *(uint32_t*)&h6, *(uint32_t*)&h7 };
    ((uint4*)dst)[i * 2]     = o0;
    ((uint4*)dst)[i * 2 + 1] = o1;
}

// ---------------------------------------------------------------------------
// Single-pass fp16 GEMM (R14 pipeline): 128x128 tile, 8 warps, K-chunks of 64,
// 3-stage cp.async, pipelined fragments, 2 CTAs/SM.
// mode 0: C = g_q/g_k/g_v (fp16).  mode 1: C = out_direct (fp32).
// ---------------------------------------------------------------------------
#define F16_TILE  16384
#define F16_STAGE 32768
#define F16_NST   3
#define SMEM_F16  (F16_NST * F16_STAGE + 1024)

__global__ __launch_bounds__(256, 2)
void gemm_f16(const float* __restrict__ b0, const float* __restrict__ b1,
              const float* __restrict__ b2, float* __restrict__ out_direct, int mode)
{
    extern __shared__ char dsm_raw[];
    char* sm = (char*)(((uintptr_t)dsm_raw + 1023) & ~(uintptr_t)1023);
    const uint32_t sb = smem_u32(sm);
    const int tid = threadIdx.x, wid = tid >> 5, lane = tid & 31;
    const int bn = blockIdx.x * 128, bm = blockIdx.y * 128, z = blockIdx.z;

    const __half *A, *W;
    if (mode == 0) {
        A = g_xf;
        W = g_wf + (size_t)z * D_MODEL * D_MODEL;
    } else {
        A = g_aof;
        W = g_wof;
    }

    const int r = tid >> 1;
    const int half_ = tid & 1;
    const __half* srcA = A + (size_t)(bm + r) * D_MODEL + half_ * 32;
    const __half* srcW = W + (size_t)(bn + r) * D_MODEL + half_ * 32;
    uint32_t sts_off[4];
#pragma unroll
    for (int s = 0; s < 4; s++) {
        uint32_t u = (uint32_t)(half_ * 4 + s);
        sts_off[s] = (uint32_t)r * 128 + ((u ^ ((uint32_t)r & 7)) << 4);
    }

    const int wm = (wid & 1) * 64;
    const int wn = (wid >> 1) * 32;

    float acc[4][4][4];
#pragma unroll
    for (int mi = 0; mi < 4; mi++)
#pragma unroll
        for (int nj = 0; nj < 4; nj++)
#pragma unroll
            for (int q = 0; q < 4; q++) acc[mi][nj][q] = 0.f;

    const uint32_t lrow = lane & 15;
    const uint32_t lsel = lane >> 4;

#pragma unroll
    for (int pc = 0; pc < 2; pc++) {
        uint32_t stb = sb + (uint32_t)pc * F16_STAGE;
#pragma unroll
        for (int s = 0; s < 4; s++) {
            CPA16(stb + sts_off[s],            srcA + pc * 64 + s * 8);
            CPA16(stb + F16_TILE + sts_off[s], srcW + pc * 64 + s * 8);
        }
        CPA_COMMIT();
    }

    int stage_c = 0;
    int stage_n = 2;
    for (int c = 0; c < 16; c++) {
        if (c == 15) { CPA_WAIT0(); } else { CPA_WAIT1(); }
        __syncthreads();

        if (c + 2 < 16) {
            uint32_t stb = sb + (uint32_t)stage_n * F16_STAGE;
#pragma unroll
            for (int s = 0; s < 4; s++) {
                CPA16(stb + sts_off[s],            srcA + (c + 2) * 64 + s * 8);
                CPA16(stb + F16_TILE + sts_off[s], srcW + (c + 2) * 64 + s * 8);
            }
            CPA_COMMIT();
        }

        const uint32_t stg = sb + (uint32_t)stage_c * F16_STAGE;
#pragma unroll
        for (int kk = 0; kk < 4; kk++) {
            const uint32_t kb = (uint32_t)kk * 2 + lsel;
            uint32_t rw0 = (uint32_t)wn + lrow;
            uint32_t rw1 = (uint32_t)(wn + 16) + lrow;
            uint32_t ra0 = (uint32_t)wm + lrow;
            uint32_t ra1 = (uint32_t)(wm + 16) + lrow;
            uint32_t ra2 = (uint32_t)(wm + 32) + lrow;
            uint32_t ra3 = (uint32_t)(wm + 48) + lrow;

            uint32_t bh0[4], bh1[4], a0[4], a1[4], a2[4], a3[4];
            LDM4(bh0, stg + F16_TILE + rw0 * 128 + ((kb ^ (rw0 & 7)) << 4));
            LDM4(bh1, stg + F16_TILE + rw1 * 128 + ((kb ^ (rw1 & 7)) << 4));
            LDM4(a0, stg + ra0 * 128 + ((kb ^ (ra0 & 7)) << 4));
            LDM4(a1, stg + ra1 * 128 + ((kb ^ (ra1 & 7)) << 4));

            MMAF16(acc[0][0], a0, bh0[0], bh0[2]);
            MMAF16(acc[0][1], a0, bh0[1], bh0[3]);
            LDM4(a2, stg + ra2 * 128 + ((kb ^ (ra2 & 7)) << 4));
            MMAF16(acc[0][2], a0, bh1[0], bh1[2]);
            MMAF16(acc[0][3], a0, bh1[1], bh1[3]);

            MMAF16(acc[1][0], a1, bh0[0], bh0[2]);
            MMAF16(acc[1][1], a1, bh0[1], bh0[3]);
            LDM4(a3, stg + ra3 * 128 + ((kb ^ (ra3 & 7)) << 4));
            MMAF16(acc[1][2], a1, bh1[0], bh1[2]);
            MMAF16(acc[1][3], a1, bh1[1], bh1[3]);

            MMAF16(acc[2][0], a2, bh0[0], bh0[2]);
            MMAF16(acc[2][1], a2, bh0[1], bh0[3]);
            MMAF16(acc[2][2], a2, bh1[0], bh1[2]);
            MMAF16(acc[2][3], a2, bh1[1], bh1[3]);
            MMAF16(acc[3][0], a3, bh0[0], bh0[2]);
            MMAF16(acc[3][1], a3, bh0[1], bh0[3]);
            MMAF16(acc[3][2], a3, bh1[0], bh1[2]);
            MMAF16(acc[3][3], a3, bh1[1], bh1[3]);
        }
        stage_c = (stage_c == F16_NST - 1) ? 0 : stage_c + 1;
        stage_n = (stage_n == F16_NST - 1) ? 0 : stage_n + 1;
    }

    if (mode == 0) {
        const float* bias = (z == 0) ? b0 : ((z == 1) ? b1 : b2);
        __half* C = (z == 0) ? g_q : ((z == 1) ? g_k : g_v);
#pragma unroll
        for (int mi = 0; mi < 4; mi++) {
            const int orow = bm + wm + mi * 16 + (lane >> 2);
#pragma unroll
            for (int nj = 0; nj < 4; nj++) {
                const int col = bn + wn + nj * 8 + ((lane & 3) << 1);
                __half2 o0 = __floats2half2_rn(acc[mi][nj][0] + bias[col],
                                               acc[mi][nj][1] + bias[col + 1]);
                __half2 o1 = __floats2half2_rn(acc[mi][nj][2] + bias[col],
                                               acc[mi][nj][3] + bias[col + 1]);
                *(uint32_t*)&C[(size_t)orow * D_MODEL + col]       = *(uint32_t*)&o0;
                *(uint32_t*)&C[(size_t)(orow + 8) * D_MODEL + col] = *(uint32_t*)&o1;
            }
        }
    } else {
        const float* bias = b0;
        float* C = out_direct;
#pragma unroll
        for (int mi = 0; mi < 4; mi++) {
            const int orow = bm + wm + mi * 16 + (lane >> 2);
#pragma unroll
            for (int nj = 0; nj < 4; nj++) {
                const int col = bn + wn + nj * 8 + ((lane & 3) << 1);
                float2 o0 = { acc[mi][nj][0] + bias[col], acc[mi][nj][1] + bias[col + 1] };
                float2 o1 = { acc[mi][nj][2] + bias[col], acc[mi][nj][3] + bias[col + 1] };
                *(float2*)&C[(size_t)orow * D_MODEL + col]       = o0;
                *(float2*)&C[(size_t)(orow + 8) * D_MODEL + col] = o1;
            }
        }
    }
}

// ---------------------------------------------------------------------------
// fp16 flash attention, fused RoPE (R15 version: 64 queries, 128 threads,
// all threads produce K and V, fp16 I/O).
// ---------------------------------------------------------------------------
__device__ __forceinline__ void rope16(float* x1, float* x2, int s, int cb, float scale) {
#pragma unroll
    for (int i = 0; i < 16; i++) {
        float invf = exp2f(-(float)(cb + i) * (13.2877123795494f / 32.f));
        float ang = (float)s * invf;
        float sn, cs;
        sincosf(ang, &sn, &cs);
        float o1 = (x1[i] * cs - x2[i] * sn) * scale;
        float o2 = (x1[i] * sn + x2[i] * cs) * scale;
        x1[i] = o1; x2[i] = o2;
    }
}

__device__ __forceinline__ void ld16h(const __half* p, float* f) {
    uint4 u0 = *(const uint4*)p;
    uint4 u1 = *(const uint4*)(p + 8);
    const uint32_t w[8] = { u0.x, u0.y, u0.z, u0.w, u1.x, u1.y, u1.z, u1.w };
#pragma unroll
    for (int i = 0; i < 8; i++) {
        float2 t = __half22float2(*(const __half2*)&w[i]);
        f[2 * i] = t.x; f[2 * i + 1] = t.y;
    }
}

__device__ __forceinline__ void store_h(char* base, int row, int cb, const float* v) {
#pragma unroll
    for (int i = 0; i < 16; i += 2) {
        uint32_t off = (uint32_t)row * 128 + (uint32_t)(cb + i) * 2;
        off ^= ((uint32_t)row & 7) << 4;
        __half2 p = __floats2half2_rn(v[i], v[i + 1]);
        *(uint32_t*)(base + off) = *(uint32_t*)&p;
    }
}

__global__ __launch_bounds__(128)
void attn_tc()
{
    __shared__ __align__(16) char sdata[24576];
    char* sQ = sdata;
    char* sK = sdata + 8192;
    char* sV = sdata + 16384;
    const uint32_t sb = smem_u32(sdata);

    const int tid = threadIdx.x, wid = tid >> 5, lane = tid & 31;
    const int q0 = blockIdx.x * 64, h = blockIdx.y, b = blockIdx.z;
    const __half* Qg = g_q + (size_t)b * SEQ * D_MODEL + h * DH;
    const __half* Kg = g_k + (size_t)b * SEQ * D_MODEL + h * DH;
    const __half* Vg = g_v + (size_t)b * SEQ * D_MODEL + h * DH;

    const int lrw = tid >> 1;
    const int lch = (tid & 1) * 16;

    {
        const __half* qp = Qg + (size_t)(q0 + lrw) * D_MODEL;
        float x1[16], x2[16];
        ld16h(qp + lch, x1);
        ld16h(qp + lch + 32, x2);
        rope16(x1, x2, q0 + lrw, lch, 0.125f);
        store_h(sQ, lrw, lch, x1);
        store_h(sQ, lrw, lch + 32, x2);
    }

    const int wq = wid * 16;
    float m0 = -1e30f, m1 = -1e30f, l0 = 0.f, l1 = 0.f;
    float acc[8][4];
#pragma unroll
    for (int nb = 0; nb < 8; nb++)
#pragma unroll
        for (int q = 0; q < 4; q++) acc[nb][q] = 0.f;

    int kv0 = q0 - WIN; if (kv0 < 0) kv0 = 0;
    const int nk = q0 + 64 - kv0;

    const int qg0 = q0 + wq + (lane >> 2);
    const int qg1 = qg0 + 8;

    for (int kb = 0; kb < nk; kb += 64) {
        const int kbase = kv0 + kb;

        __syncthreads();
        {
            const __half* kp = Kg + (size_t)(kbase + lrw) * D_MODEL;
            float x1[16], x2[16];
            ld16h(kp + lch, x1);
            ld16h(kp + lch + 32, x2);
            rope16(x1, x2, kbase + lrw, lch, 1.0f);
            store_h(sK, lrw, lch, x1);
            store_h(sK, lrw, lch + 32, x2);

            const __half* vp = Vg + (size_t)(kbase + lrw) * D_MODEL;
            const int vc = (tid & 1) * 32;
            float va[16], vb[16];
            ld16h(vp + vc, va);
            ld16h(vp + vc + 16, vb);
            store_h(sV, lrw, vc, va);
            store_h(sV, lrw, vc + 16, vb);
        }
        __syncthreads();

        float S[8][4];
#pragma unroll
        for (int nb = 0; nb < 8; nb++)
#pragma unroll
            for (int q = 0; q < 4; q++) S[nb][q] = 0.f;

#pragma unroll
        for (int ks = 0; ks < 4; ks++) {
            const uint32_t acb  = (uint32_t)ks * 32 + ((uint32_t)(lane >> 4) << 4);
            const uint32_t arow = (uint32_t)wq + (lane & 15);
            const uint32_t aoff = arow * 128 + (acb ^ ((arow & 7) << 4));
            uint32_t ah[4];
            LDM4(ah, sb + aoff);
#pragma unroll
            for (int nb2 = 0; nb2 < 4; nb2++) {
                const uint32_t brow = (uint32_t)nb2 * 16 + (lane & 15);
                const uint32_t boff = brow * 128 + (acb ^ ((brow & 7) << 4));
                uint32_t bh[4];
                LDM4(bh, sb + 8192 + boff);
                MMAF16(S[nb2 * 2],     ah, bh[0], bh[2]);
                MMAF16(S[nb2 * 2 + 1], ah, bh[1], bh[3]);
            }
        }

#pragma unroll
        for (int nb = 0; nb < 8; nb++) {
            const int kg = kbase + nb * 8 + ((lane & 3) << 1);
            if (kg     > qg0 || kg     < qg0 - WIN) S[nb][0] = -1e30f;
            if (kg + 1 > qg0 || kg + 1 < qg0 - WIN) S[nb][1] = -1e30f;
            if (kg     > qg1 || kg     < qg1 - WIN) S[nb][2] = -1e30f;
            if (kg + 1 > qg1 || kg + 1 < qg1 - WIN) S[nb][3] = -1e30f;
        }
        float mx0 = -1e30f, mx1 = -1e30f;
#pragma unroll
        for (int nb = 0; nb < 8; nb++) {
            mx0 = fmaxf(mx0, fmaxf(S[nb][0], S[nb][1]));
            mx1 = fmaxf(mx1, fmaxf(S[nb][2], S[nb][3]));
        }
        mx0 = fmaxf(mx0, __shfl_xor_sync(0xffffffffu, mx0, 1));
        mx0 = fmaxf(mx0, __shfl_xor_sync(0xffffffffu, mx0, 2));
        mx1 = fmaxf(mx1, __shfl_xor_sync(0xffffffffu, mx1, 1));
        mx1 = fmaxf(mx1, __shfl_xor_sync(0xffffffffu, mx1, 2));

        const float mn0 = fmaxf(m0, mx0), mn1 = fmaxf(m1, mx1);
        const float e0 = __expf(m0 - mn0), e1 = __expf(m1 - mn1);
        m0 = mn0; m1 = mn1;

        float s0 = 0.f, s1 = 0.f;
#pragma unroll
        for (int nb = 0; nb < 8; nb++) {
            S[nb][0] = __expf(S[nb][0] - m0); s0 += S[nb][0];
            S[nb][1] = __expf(S[nb][1] - m0); s0 += S[nb][1];
            S[nb][2] = __expf(S[nb][2] - m1); s1 += S[nb][2];
            S[nb][3] = __expf(S[nb][3] - m1); s1 += S[nb][3];
        }
        s0 += __shfl_xor_sync(0xffffffffu, s0, 1);
        s0 += __shfl_xor_sync(0xffffffffu, s0, 2);
        s1 += __shfl_xor_sync(0xffffffffu, s1, 1);
        s1 += __shfl_xor_sync(0xffffffffu, s1, 2);
        l0 = l0 * e0 + s0;
        l1 = l1 * e1 + s1;
#pragma unroll
        for (int nb = 0; nb < 8; nb++) {
            acc[nb][0] *= e0; acc[nb][1] *= e0;
            acc[nb][2] *= e1; acc[nb][3] *= e1;
        }

#pragma unroll
        for (int j = 0; j < 4; j++) {
            uint32_t pa[4];
            __half2 p0 = __floats2half2_rn(S[2 * j][0],     S[2 * j][1]);
            __half2 p1 = __floats2half2_rn(S[2 * j][2],     S[2 * j][3]);
            __half2 p2 = __floats2half2_rn(S[2 * j + 1][0], S[2 * j + 1][1]);
            __half2 p3 = __floats2half2_rn(S[2 * j + 1][2], S[2 * j + 1][3]);
            pa[0] = *(uint32_t*)&p0; pa[1] = *(uint32_t*)&p1;
            pa[2] = *(uint32_t*)&p2; pa[3] = *(uint32_t*)&p3;

            const uint32_t vrow = (uint32_t)j * 16 + (lane & 15);
#pragma unroll
            for (int nb2 = 0; nb2 < 4; nb2++) {
                const uint32_t vcb = (uint32_t)nb2 * 32 + ((uint32_t)(lane >> 4) << 4);
                const uint32_t boff = vrow * 128 + (vcb ^ ((vrow & 7) << 4));
                uint32_t vh[4];
                LDM4T(vh, sb + 16384 + boff);
                MMAF16(acc[nb2 * 2],     pa, vh[0], vh[1]);
                MMAF16(acc[nb2 * 2 + 1], pa, vh[2], vh[3]);
            }
        }
    }

    const float inv0 = 1.f / l0, inv1 = 1.f / l1;
#pragma unroll
    for (int nb = 0; nb < 8; nb++) {
        const int col = h * DH + nb * 8 + ((lane & 3) << 1);
        const size_t i0 = ((size_t)b * SEQ + qg0) * D_MODEL + col;
        const size_t i1 = ((size_t)b * SEQ + qg1) * D_MODEL + col;
        __half2 p0 = __floats2half2_rn(acc[nb][0] * inv0, acc[nb][1] * inv0);
        __half2 p1 = __floats2half2_rn(acc[nb][2] * inv1, acc[nb][3] * inv1);
        *(uint32_t*)(g_aof + i0) = *(uint32_t*)&p0;
        *(uint32_t*)(g_aof + i1) = *(uint32_t*)&p1;
    }
}

// ---------------------------------------------------------------------------
extern "C" void kernel_launch(void* const* d_in, const int* in_sizes, int n_in,
                              void* d_out, int out_size)
{
    const float* x  = (const float*)d_in[0];
    const float* Wq = (const float*)d_in[1];
    const float* bq = (const float*)d_in[2];
    const float* Wk = (const float*)d_in[3];
    const float* bk = (const float*)d_in[4];
    const float* Wv = (const float*)d_in[5];
    const float* bv = (const float*)d_in[6];
    const float* Wo = (const float*)d_in[7];
    const float* bo = (const float*)d_in[8];
    float* out = (float*)d_out;

    cudaFuncSetAttribute(gemm_f16, cudaFuncAttributeMaxDynamicSharedMemorySize, SMEM_F16);

    conv_all<<<2048, 256>>>(x, Wq, Wk, Wv, Wo);

    gemm_f16<<<dim3(8, 32, 3), 256, SMEM_F16>>>(bq, bk, bv, nullptr, 0);

    dim3 agrid(SEQ / 64, NHEADS, BATCH);   // (32, 16, 2)
    attn_tc<<<agrid, 128>>>();

    gemm_f16<<<dim3(8, 32, 1), 256, SMEM_F16>>>(bo, nullptr, nullptr, out, 1);
}